// round 9
// baseline (speedup 1.0000x reference)
#include <cuda_runtime.h>
#include <cuda_fp16.h>
#include <cstdint>

#define HEADS   8
#define NNODES  50000
#define NBLK    296     // 2 blocks/SM x 148 SMs -> exactly one resident wave
#define NTHR    1024    // 64 warps per SM total

__device__ float    g_segsum[NNODES * HEADS];   // sums, then reciprocals (in place)
__device__ int      g_is64;                     // index dtype flag
__device__ unsigned g_bar;                      // grid barrier counter

// ---------------------------------------------------------------------------
// setup: zero seg_sum, reset barrier, sniff index dtype.
// int64 little-endian values < 50000 => every odd int32 word is 0.
// ---------------------------------------------------------------------------
__global__ void setup_kernel(const int* __restrict__ idx_raw)
{
    int i = blockIdx.x * blockDim.x + threadIdx.x;
    if (i < NNODES * HEADS) g_segsum[i] = 0.0f;

    if (blockIdx.x == 0) {
        if (threadIdx.x == 0) g_bar = 0;
        __shared__ int nz;
        if (threadIdx.x == 0) nz = 0;
        __syncthreads();
        int pos = 2 * threadIdx.x + 1;
        if (pos < 256 && idx_raw[pos] != 0) nz = 1;   // benign race
        __syncthreads();
        if (threadIdx.x == 0) g_is64 = (nz == 0) ? 1 : 0;
    }
}

// Software grid barrier: safe because the grid is exactly one resident wave
// (launch_bounds(1024,2): regs<=32; smem 86.5KB*2 = 173KB < 228KB per SM).
__device__ __forceinline__ void gridbar(unsigned target)
{
    __syncthreads();
    if (threadIdx.x == 0) {
        __threadfence();                    // release prior writes/atomics
        atomicAdd(&g_bar, 1);
        while (*((volatile unsigned*)&g_bar) < target) { }
    }
    __syncthreads();                        // acquire for the whole block
}

// ---------------------------------------------------------------------------
// Fused kernel. Block b owns edges [b*chunk, b*chunk+nloc).
// Phase 1: warp handles 2 edges/iter: dot + exp; ex fp32 for atomics,
//          fp16 in smem for phase 3. Atomics deduped (index sorted).
// Phase 2: seg_sum -> 1/(seg_sum+1e-16) in place.
// Phase 3: out[e,h] = ex_smem[e,h] * rcp_segsum[idx[e],h], coalesced fp32.
// ---------------------------------------------------------------------------
extern __shared__ __half ex_s[];            // chunk * 8 halves

__global__ void __launch_bounds__(NTHR, 2)
fused_kernel(const float4* __restrict__ q,
             const float4* __restrict__ k,
             const void*  __restrict__ idx_raw,
             float* __restrict__ out,
             int E, int chunk)
{
    const int tid  = threadIdx.x;
    const int lane = tid & 31;
    const int warp = tid >> 5;              // 0..31
    const int base = blockIdx.x * chunk;
    int nloc = E - base;                    // chunk and E are multiples of 2
    if (nloc > chunk) nloc = chunk;
    if (nloc < 0)     nloc = 0;
    const bool is64 = (g_is64 != 0);

    // ---------------- phase 1 ----------------
    for (int g = warp * 2; g < nloc; g += 32 * 2) {
        const int e0 = base + g;

        int node0, node1;
        if (is64) {
            const long long* p = (const long long*)idx_raw;
            node0 = (int)p[e0];
            node1 = (int)p[e0 + 1];
        } else {
            const int* p = (const int*)idx_raw;
            node0 = p[e0];
            node1 = p[e0 + 1];
        }

        // 4 independent 16B loads in flight per warp
        long ba = (long)e0 * 32 + lane;
        float4 a0 = q[ba];
        float4 b0 = k[ba];
        float4 a1 = q[ba + 32];
        float4 b1 = k[ba + 32];

        float r0 = a0.x * b0.x + a0.y * b0.y + a0.z * b0.z + a0.w * b0.w;
        float r1 = a1.x * b1.x + a1.y * b1.y + a1.z * b1.z + a1.w * b1.w;
        r0 += __shfl_xor_sync(0xffffffffu, r0, 1);
        r1 += __shfl_xor_sync(0xffffffffu, r1, 1);
        r0 += __shfl_xor_sync(0xffffffffu, r0, 16);
        r1 += __shfl_xor_sync(0xffffffffu, r1, 16);
        float ex0 = __expf(r0 * 0.35355339059327373f);   // * C^-0.5
        float ex1 = __expf(r1 * 0.35355339059327373f);

        // Transpose: lane d in [0,16) wants (edge i=d>>3, head h=d&7),
        // whose value lives at source lane 2h. Contiguous fp16 smem store.
        {
            int src = (lane & 7) * 2;
            float t0 = __shfl_sync(0xffffffffu, ex0, src);
            float t1 = __shfl_sync(0xffffffffu, ex1, src);
            if (lane < 16)
                ex_s[g * 8 + lane] = __float2half_rn(lane < 8 ? t0 : t1);
        }

        // Segment-sum atomics (fp32), deduped across the 2 sorted edges.
        if (lane < 16 && !(lane & 1)) {
            int h = lane >> 1;
            if (node0 == node1) {
                atomicAdd(&g_segsum[node0 * HEADS + h], ex0 + ex1);
            } else {
                atomicAdd(&g_segsum[node0 * HEADS + h], ex0);
                atomicAdd(&g_segsum[node1 * HEADS + h], ex1);
            }
        }
    }

    // ---------------- phase 2: reciprocal ----------------
    gridbar(NBLK);
    {
        int gt = blockIdx.x * NTHR + tid;
        for (int i = gt; i < NNODES * HEADS; i += NBLK * NTHR)
            g_segsum[i] = 1.0f / (g_segsum[i] + 1e-16f);
    }
    gridbar(2 * NBLK);

    // ---------------- phase 3: normalize + write ----------------
    for (int el = tid; el < nloc; el += NTHR) {
        int e = base + el;
        int node = is64 ? (int)((const long long*)idx_raw)[e]
                        : ((const int*)idx_raw)[e];

        const float4* s = (const float4*)&g_segsum[node * HEADS];
        float4 s0 = s[0], s1 = s[1];

        const __half2* hp = (const __half2*)&ex_s[el * 8];
        float2 e01 = __half22float2(hp[0]);
        float2 e23 = __half22float2(hp[1]);
        float2 e45 = __half22float2(hp[2]);
        float2 e67 = __half22float2(hp[3]);

        float4 o0 = make_float4(e01.x * s0.x, e01.y * s0.y,
                                e23.x * s0.z, e23.y * s0.w);
        float4 o1 = make_float4(e45.x * s1.x, e45.y * s1.y,
                                e67.x * s1.z, e67.y * s1.w);

        float4* op = (float4*)&out[(long)e * HEADS];
        op[0] = o0;
        op[1] = o1;
    }
}

extern "C" void kernel_launch(void* const* d_in, const int* in_sizes, int n_in,
                              void* d_out, int out_size)
{
    const float4* q   = (const float4*)d_in[0];
    const float4* k   = (const float4*)d_in[1];
    const void*   idx = d_in[2];

    int E = in_sizes[0] / 128;   // q is [E, 2, 8, 8] fp32

    // chunk: per-block edge count, multiple of 4
    int chunk = ((E + NBLK * 4 - 1) / (NBLK * 4)) * 4;    // 5408 for E=1.6M
    size_t smem = (size_t)chunk * HEADS * sizeof(__half); // 86528 B

    static bool attr_done = false;
    if (!attr_done) {
        cudaFuncSetAttribute(fused_kernel,
                             cudaFuncAttributeMaxDynamicSharedMemorySize,
                             (int)smem);
        attr_done = true;
    }

    setup_kernel<<<(NNODES * HEADS + 255) / 256, 256>>>((const int*)idx);
    fused_kernel<<<NBLK, NTHR, smem>>>(q, k, idx, (float*)d_out, E, chunk);
}

// round 13
// speedup vs baseline: 1.0705x; 1.0705x over previous
#include <cuda_runtime.h>
#include <cuda_fp16.h>
#include <cstdint>

#define HEADS   8
#define NNODES  50000
#define NBLK    296     // 2 blocks/SM x 148 SMs -> exactly one resident wave
#define NTHR    512     // 16 warps/block; 4 edges/warp (best phase-1 shape, R6)

__device__ float    g_segsum[NNODES * HEADS];   // sums, then reciprocals (in place)
__device__ int      g_is64;                     // index dtype flag
__device__ unsigned g_bar;                      // grid barrier counter

// ---------------------------------------------------------------------------
// setup: zero seg_sum, reset barrier, sniff index dtype.
// int64 little-endian values < 50000 => every odd int32 word is 0.
// ---------------------------------------------------------------------------
__global__ void setup_kernel(const int* __restrict__ idx_raw)
{
    int i = blockIdx.x * blockDim.x + threadIdx.x;
    if (i < NNODES * HEADS) g_segsum[i] = 0.0f;

    if (blockIdx.x == 0) {
        if (threadIdx.x == 0) g_bar = 0;
        __shared__ int nz;
        if (threadIdx.x == 0) nz = 0;
        __syncthreads();
        int pos = 2 * threadIdx.x + 1;
        if (pos < 256 && idx_raw[pos] != 0) nz = 1;   // benign race
        __syncthreads();
        if (threadIdx.x == 0) g_is64 = (nz == 0) ? 1 : 0;
    }
}

// Software grid barrier: safe because the grid is exactly one resident wave
// (launch_bounds(512,2): regs<=64; smem 97.3KB*2 = 194.7KB < 228KB per SM).
__device__ __forceinline__ void gridbar(unsigned target)
{
    __syncthreads();
    if (threadIdx.x == 0) {
        __threadfence();                    // release prior writes/atomics
        atomicAdd(&g_bar, 1);
        while (*((volatile unsigned*)&g_bar) < target) { }
    }
    __syncthreads();                        // acquire for the whole block
}

// ---------------------------------------------------------------------------
// Fused kernel. Block b owns edges [b*chunk, b*chunk+nloc).
// Phase 1: warp handles 4 edges/iter: dot + exp. ex fp32 for atomics,
//          fp16 in smem for phase 3; node ids stashed as uint16 in smem.
//          Atomics deduped over the 4 sorted edges. q/k loads use .cs
//          (streaming, single-use).
// Phase 2: seg_sum -> 1/(seg_sum+1e-16) in place.
// Phase 3: out[e,h] = ex_s[e,h] * rcp_segsum[node_s[e],h] -- no gmem idx read.
// ---------------------------------------------------------------------------
extern __shared__ char smem_raw[];

__global__ void __launch_bounds__(NTHR, 2)
fused_kernel(const float4* __restrict__ q,
             const float4* __restrict__ k,
             const void*  __restrict__ idx_raw,
             float* __restrict__ out,
             int E, int chunk)
{
    __half*         ex_s   = (__half*)smem_raw;                    // chunk*8
    unsigned short* node_s = (unsigned short*)(smem_raw + (size_t)chunk * HEADS * 2);

    const int tid  = threadIdx.x;
    const int lane = tid & 31;
    const int warp = tid >> 5;              // 0..15
    const int base = blockIdx.x * chunk;
    int nloc = E - base;                    // chunk and E are multiples of 4
    if (nloc > chunk) nloc = chunk;
    if (nloc < 0)     nloc = 0;
    const bool is64 = (g_is64 != 0);

    // ---------------- phase 1 ----------------
    for (int g = warp * 4; g < nloc; g += 16 * 4) {
        const int e0 = base + g;

        int node[4];
        if (is64) {
            const long long* p = (const long long*)idx_raw;
            #pragma unroll
            for (int i = 0; i < 4; i++) node[i] = (int)p[e0 + i];
        } else {
            const int* p = (const int*)idx_raw;
            #pragma unroll
            for (int i = 0; i < 4; i++) node[i] = p[e0 + i];
        }
        if (lane < 4) node_s[g + lane] = (unsigned short)node[lane];

        // 8 independent 16B streaming loads in flight per warp
        float4 a[4], b[4];
        #pragma unroll
        for (int i = 0; i < 4; i++) {
            long ba = (long)(e0 + i) * 32 + lane;
            a[i] = __ldcs(&q[ba]);
            b[i] = __ldcs(&k[ba]);
        }

        float ex[4];
        #pragma unroll
        for (int i = 0; i < 4; i++) {
            float r = a[i].x * b[i].x + a[i].y * b[i].y
                    + a[i].z * b[i].z + a[i].w * b[i].w;
            r += __shfl_xor_sync(0xffffffffu, r, 1);
            r += __shfl_xor_sync(0xffffffffu, r, 16);
            ex[i] = __expf(r * 0.35355339059327373f);   // * C^-0.5
        }

        // Transpose: dest lane d holds (edge i=d>>3, head h=d&7), whose value
        // lives at source lane 2h. Contiguous 32-lane fp16 smem store.
        {
            int src = (lane & 7) * 2;
            float t0 = __shfl_sync(0xffffffffu, ex[0], src);
            float t1 = __shfl_sync(0xffffffffu, ex[1], src);
            float t2 = __shfl_sync(0xffffffffu, ex[2], src);
            float t3 = __shfl_sync(0xffffffffu, ex[3], src);
            float v = (lane < 8) ? t0 : (lane < 16) ? t1 : (lane < 24) ? t2 : t3;
            ex_s[g * 8 + lane] = __float2half_rn(v);
        }

        // Segment-sum atomics (fp32), deduped over the 4 sorted edges.
        if (lane < 16 && !(lane & 1)) {
            int h = lane >> 1;
            float acc = ex[0];
            int cur = node[0];
            #pragma unroll
            for (int i = 1; i < 4; i++) {
                if (node[i] == cur) {
                    acc += ex[i];
                } else {
                    atomicAdd(&g_segsum[cur * HEADS + h], acc);
                    cur = node[i];
                    acc = ex[i];
                }
            }
            atomicAdd(&g_segsum[cur * HEADS + h], acc);
        }
    }

    // ---------------- phase 2: reciprocal ----------------
    gridbar(NBLK);
    {
        int gt = blockIdx.x * NTHR + tid;
        for (int i = gt; i < NNODES * HEADS; i += NBLK * NTHR)
            g_segsum[i] = 1.0f / (g_segsum[i] + 1e-16f);
    }
    gridbar(2 * NBLK);

    // ---------------- phase 3: normalize + write ----------------
    for (int el = tid; el < nloc; el += NTHR) {
        int e = base + el;
        int node = node_s[el];

        const float4* s = (const float4*)&g_segsum[node * HEADS];
        float4 s0 = __ldg(s);
        float4 s1 = __ldg(s + 1);

        const __half2* hp = (const __half2*)&ex_s[el * 8];
        float2 e01 = __half22float2(hp[0]);
        float2 e23 = __half22float2(hp[1]);
        float2 e45 = __half22float2(hp[2]);
        float2 e67 = __half22float2(hp[3]);

        float4 o0 = make_float4(e01.x * s0.x, e01.y * s0.y,
                                e23.x * s0.z, e23.y * s0.w);
        float4 o1 = make_float4(e45.x * s1.x, e45.y * s1.y,
                                e67.x * s1.z, e67.y * s1.w);

        float4* op = (float4*)&out[(long)e * HEADS];
        op[0] = o0;
        op[1] = o1;
    }
}

extern "C" void kernel_launch(void* const* d_in, const int* in_sizes, int n_in,
                              void* d_out, int out_size)
{
    const float4* q   = (const float4*)d_in[0];
    const float4* k   = (const float4*)d_in[1];
    const void*   idx = d_in[2];

    int E = in_sizes[0] / 128;   // q is [E, 2, 8, 8] fp32

    // chunk: per-block edge count, multiple of 4
    int chunk = ((E + NBLK * 4 - 1) / (NBLK * 4)) * 4;    // 5408 for E=1.6M
    // smem: ex fp16 (chunk*8*2 B) + node u16 (chunk*2 B)
    size_t smem = (size_t)chunk * HEADS * sizeof(__half)
                + (size_t)chunk * sizeof(unsigned short);  // 97344 B

    static bool attr_done = false;
    if (!attr_done) {
        cudaFuncSetAttribute(fused_kernel,
                             cudaFuncAttributeMaxDynamicSharedMemorySize,
                             (int)smem);
        attr_done = true;
    }

    setup_kernel<<<(NNODES * HEADS + 255) / 256, 256>>>((const int*)idx);
    fused_kernel<<<NBLK, NTHR, smem>>>(q, k, idx, (float*)d_out, E, chunk);
}